// round 5
// baseline (speedup 1.0000x reference)
#include <cuda_runtime.h>

// LGCN layer: out = D_in^{-1/2} * A * D_out^{-1/2} * x
// Round 5: single persistent kernel, 5 software grid barriers, no launch gaps.

#define DFEAT 96
#define DV    24          // float4 chunks per row
#define MAXN  50048
#define MAXE  800000
#define NB    148         // one block per SM, all resident
#define BT    1024
#define NT    (NB * BT)

__device__ int      g_outdeg[MAXN];
__device__ int      g_indeg[MAXN];
__device__ float    g_rsout[MAXN];
__device__ int      g_rowstart[MAXN + 1];
__device__ int      g_cursor[MAXN];
__device__ int      g_csr[MAXE];
__device__ int      g_blocksum[NB];
__device__ int      g_is64;
__device__ unsigned g_cnt[8];     // barrier counters; self-resetting each launch

// Grid barrier k. After passing, block 0 resets counter k-1 (provably drained:
// everyone arriving at k has passed k's predecessor's spin).
__device__ __forceinline__ void gbar(int k) {
    __syncthreads();
    if (threadIdx.x == 0) {
        __threadfence();
        atomicAdd(&g_cnt[k], 1u);
        volatile unsigned* p = (volatile unsigned*)&g_cnt[k];
        while (*p < NB) { }
        if (blockIdx.x == 0 && k >= 1) ((volatile unsigned*)g_cnt)[k - 1] = 0;
        __threadfence();
    }
    __syncthreads();
}

// Final barrier: uses helper counter g_cnt[LAST+1]; the LAST block to pass
// resets both (safe: all blocks already exited the spin).
__device__ __forceinline__ void gbar_last(int k) {
    __syncthreads();
    if (threadIdx.x == 0) {
        __threadfence();
        atomicAdd(&g_cnt[k], 1u);
        volatile unsigned* p = (volatile unsigned*)&g_cnt[k];
        while (*p < NB) { }
        unsigned r = atomicAdd(&g_cnt[k + 1], 1u);
        if (r == NB - 1) {
            ((volatile unsigned*)g_cnt)[k]     = 0;
            ((volatile unsigned*)g_cnt)[k + 1] = 0;
            ((volatile unsigned*)g_cnt)[k - 1] = 0;
        }
        __threadfence();
    }
    __syncthreads();
}

__device__ __forceinline__ void load_pair(const void* src, const void* dst,
                                          int t, int n_edges, int is64,
                                          int& s0, int& s1, int& d0, int& d1,
                                          bool& two) {
    int e0 = t * 2;
    two = (e0 + 1 < n_edges);
    if (is64) {
        if (two) {
            ulonglong2 sv = ((const ulonglong2*)src)[t];
            ulonglong2 dv = ((const ulonglong2*)dst)[t];
            s0 = (int)sv.x; s1 = (int)sv.y; d0 = (int)dv.x; d1 = (int)dv.y;
        } else {
            s0 = (int)((const long long*)src)[e0]; s1 = 0;
            d0 = (int)((const long long*)dst)[e0]; d1 = 0;
        }
    } else {
        if (two) {
            int2 sv = ((const int2*)src)[t];
            int2 dv = ((const int2*)dst)[t];
            s0 = sv.x; s1 = sv.y; d0 = dv.x; d1 = dv.y;
        } else {
            s0 = ((const int*)src)[e0]; s1 = 0;
            d0 = ((const int*)dst)[e0]; d1 = 0;
        }
    }
}

__global__ void __launch_bounds__(BT, 1) k_fused(
    const float4* __restrict__ x, const void* __restrict__ src,
    const void* __restrict__ dst, float4* __restrict__ out,
    int n_nodes, int n_edges)
{
    __shared__ int s_warpsum[32];
    __shared__ int s_blockoff;

    const int tid  = threadIdx.x;
    const int gtid = blockIdx.x * BT + tid;
    const int lane = tid & 31, wid = tid >> 5;

    // ── Phase 0: zero degrees, detect index width ──
    for (int i = gtid; i < n_nodes; i += NT) { g_outdeg[i] = 0; g_indeg[i] = 0; }
    if (gtid == 0) {
        const unsigned long long* p = (const unsigned long long*)src;
        int is64 = 1;
        int k = n_edges < 64 ? n_edges : 64;
        for (int j = 0; j < k; j++)
            if (p[j] >= (unsigned long long)n_nodes) { is64 = 0; break; }
        g_is64 = is64;
    }
    gbar(0);

    const int is64  = g_is64;
    const int npair = (n_edges + 1) >> 1;

    // ── Phase 1: degree histograms ──
    for (int t = gtid; t < npair; t += NT) {
        int s0, s1, d0, d1; bool two;
        load_pair(src, dst, t, n_edges, is64, s0, s1, d0, d1, two);
        atomicAdd(&g_outdeg[s0], 1);
        atomicAdd(&g_indeg[d0], 1);
        if (two) { atomicAdd(&g_outdeg[s1], 1); atomicAdd(&g_indeg[d1], 1); }
    }
    gbar(1);

    // ── Phase 2a: per-block chunk sum of indeg (value kept in register) ──
    const int chunk = (n_nodes + NB - 1) / NB;        // 338 for n=50000
    const int base  = blockIdx.x * chunk;
    int rem  = n_nodes - base;
    int cntn = rem < 0 ? 0 : (rem < chunk ? rem : chunk);
    int v = (tid < cntn) ? g_indeg[base + tid] : 0;
    {
        int r = v;
        #pragma unroll
        for (int o = 16; o > 0; o >>= 1) r += __shfl_down_sync(0xFFFFFFFFu, r, o);
        if (lane == 0) s_warpsum[wid] = r;
        __syncthreads();
        if (wid == 0) {
            int a = s_warpsum[lane];
            #pragma unroll
            for (int o = 16; o > 0; o >>= 1) a += __shfl_down_sync(0xFFFFFFFFu, a, o);
            if (lane == 0) g_blocksum[blockIdx.x] = a;
        }
    }
    gbar(2);

    // ── Phase 2b: block offset + local exclusive scan -> rowstart/cursor/rsout ──
    if (wid == 31) {
        int acc = 0;
        for (int b = lane; b < blockIdx.x; b += 32) acc += g_blocksum[b];
        #pragma unroll
        for (int o = 16; o > 0; o >>= 1) acc += __shfl_down_sync(0xFFFFFFFFu, acc, o);
        if (lane == 0) s_blockoff = acc;
    }
    __syncthreads();
    int inc = v;
    #pragma unroll
    for (int o = 1; o < 32; o <<= 1) {
        int t = __shfl_up_sync(0xFFFFFFFFu, inc, o);
        if (lane >= o) inc += t;
    }
    if (lane == 31) s_warpsum[wid] = inc;
    __syncthreads();
    if (wid == 0) {
        int orig = s_warpsum[lane];
        int sc = orig;
        #pragma unroll
        for (int o = 1; o < 32; o <<= 1) {
            int t = __shfl_up_sync(0xFFFFFFFFu, sc, o);
            if (lane >= o) sc += t;
        }
        s_warpsum[lane] = sc - orig;
    }
    __syncthreads();
    int excl = inc - v + s_warpsum[wid] + s_blockoff;
    if (tid < cntn) {
        int i = base + tid;
        g_rowstart[i] = excl;
        g_cursor[i]   = excl;
        int od = g_outdeg[i]; if (od < 1) od = 1;
        g_rsout[i] = rsqrtf((float)od);
    }
    if (base + tid == n_nodes - 1) g_rowstart[n_nodes] = excl + v;
    gbar(3);

    // ── Phase 3: fill CSR ──
    for (int t = gtid; t < npair; t += NT) {
        int s0, s1, d0, d1; bool two;
        load_pair(src, dst, t, n_edges, is64, s0, s1, d0, d1, two);
        int p0 = atomicAdd(&g_cursor[d0], 1);
        g_csr[p0] = s0;
        if (two) {
            int p1 = atomicAdd(&g_cursor[d1], 1);
            g_csr[p1] = s1;
        }
    }
    gbar_last(4);

    // ── Phase 4: warp-per-node gather, 2-edge unroll ──
    const int gw     = gtid >> 5;
    const int nwarps = NB * (BT / 32);
    for (int w = gw; w < n_nodes; w += nwarps) {
        int beg = g_rowstart[w];
        int end = g_rowstart[w + 1];
        float4 acc = make_float4(0.f, 0.f, 0.f, 0.f);
        int j = beg;
        for (; j + 2 <= end; j += 2) {
            int s0 = g_csr[j];
            int s1 = g_csr[j + 1];
            float c0 = g_rsout[s0];
            float c1 = g_rsout[s1];
            if (lane < DV) {
                float4 v0 = x[s0 * DV + lane];
                float4 v1 = x[s1 * DV + lane];
                acc.x = fmaf(v0.x, c0, acc.x); acc.y = fmaf(v0.y, c0, acc.y);
                acc.z = fmaf(v0.z, c0, acc.z); acc.w = fmaf(v0.w, c0, acc.w);
                acc.x = fmaf(v1.x, c1, acc.x); acc.y = fmaf(v1.y, c1, acc.y);
                acc.z = fmaf(v1.z, c1, acc.z); acc.w = fmaf(v1.w, c1, acc.w);
            }
        }
        if (j < end) {
            int s = g_csr[j];
            float c = g_rsout[s];
            if (lane < DV) {
                float4 vv = x[s * DV + lane];
                acc.x = fmaf(vv.x, c, acc.x); acc.y = fmaf(vv.y, c, acc.y);
                acc.z = fmaf(vv.z, c, acc.z); acc.w = fmaf(vv.w, c, acc.w);
            }
        }
        int deg = end - beg; if (deg < 1) deg = 1;
        float rsin = rsqrtf((float)deg);
        if (lane < DV) {
            acc.x *= rsin; acc.y *= rsin; acc.z *= rsin; acc.w *= rsin;
            out[w * DV + lane] = acc;
        }
    }
}

extern "C" void kernel_launch(void* const* d_in, const int* in_sizes, int n_in,
                              void* d_out, int out_size) {
    const float* x   = (const float*)d_in[0];
    const void*  src = d_in[1];
    const void*  dst = d_in[2];
    float* out = (float*)d_out;

    int n_nodes = in_sizes[0] / DFEAT;   // 50000
    int n_edges = in_sizes[1];           // 800000

    k_fused<<<NB, BT>>>((const float4*)x, src, dst, (float4*)out,
                        n_nodes, n_edges);
}

// round 6
// speedup vs baseline: 1.1690x; 1.1690x over previous
#include <cuda_runtime.h>

// LGCN layer: out = D_in^{-1/2} * A * D_out^{-1/2} * x
// Round 6: persistent aux kernel (zero/detect/deg/scan/fill, 4 grid barriers)
//          + standalone high-occupancy gather (R4 config).

#define DFEAT 96
#define DV    24          // float4 chunks per row
#define MAXN  50048
#define MAXE  800000
#define NB    148         // aux: one block per SM
#define BT    1024
#define NT    (NB * BT)

__device__ int      g_outdeg[MAXN];
__device__ int      g_indeg[MAXN];
__device__ float    g_rsout[MAXN];
__device__ int      g_rowstart[MAXN + 1];
__device__ int      g_cursor[MAXN];
__device__ int      g_csr[MAXE];
__device__ int      g_blocksum[NB];
__device__ int      g_is64;
__device__ unsigned g_cnt[8];     // barrier counters; self-resetting each launch

// Grid barrier k. After passing, block 0 resets counter k-1 (provably drained).
__device__ __forceinline__ void gbar(int k) {
    __syncthreads();
    if (threadIdx.x == 0) {
        __threadfence();
        atomicAdd(&g_cnt[k], 1u);
        volatile unsigned* p = (volatile unsigned*)&g_cnt[k];
        while (*p < NB) { }
        if (blockIdx.x == 0 && k >= 1) ((volatile unsigned*)g_cnt)[k - 1] = 0;
        __threadfence();
    }
    __syncthreads();
}

// Final barrier: helper counter g_cnt[k+1]; last block through resets k-1,k,k+1.
__device__ __forceinline__ void gbar_last(int k) {
    __syncthreads();
    if (threadIdx.x == 0) {
        __threadfence();
        atomicAdd(&g_cnt[k], 1u);
        volatile unsigned* p = (volatile unsigned*)&g_cnt[k];
        while (*p < NB) { }
        unsigned r = atomicAdd(&g_cnt[k + 1], 1u);
        if (r == NB - 1) {
            ((volatile unsigned*)g_cnt)[k]     = 0;
            ((volatile unsigned*)g_cnt)[k + 1] = 0;
            ((volatile unsigned*)g_cnt)[k - 1] = 0;
        }
        __threadfence();
    }
    __syncthreads();
}

__device__ __forceinline__ void load_pair(const void* src, const void* dst,
                                          int t, int n_edges, int is64,
                                          int& s0, int& s1, int& d0, int& d1,
                                          bool& two) {
    int e0 = t * 2;
    two = (e0 + 1 < n_edges);
    if (is64) {
        if (two) {
            ulonglong2 sv = ((const ulonglong2*)src)[t];
            ulonglong2 dv = ((const ulonglong2*)dst)[t];
            s0 = (int)sv.x; s1 = (int)sv.y; d0 = (int)dv.x; d1 = (int)dv.y;
        } else {
            s0 = (int)((const long long*)src)[e0]; s1 = 0;
            d0 = (int)((const long long*)dst)[e0]; d1 = 0;
        }
    } else {
        if (two) {
            int2 sv = ((const int2*)src)[t];
            int2 dv = ((const int2*)dst)[t];
            s0 = sv.x; s1 = sv.y; d0 = dv.x; d1 = dv.y;
        } else {
            s0 = ((const int*)src)[e0]; s1 = 0;
            d0 = ((const int*)dst)[e0]; d1 = 0;
        }
    }
}

// ── Aux: zero + detect + degrees + scan + CSR fill, one persistent launch ──
__global__ void __launch_bounds__(BT, 1) k_aux(
    const void* __restrict__ src, const void* __restrict__ dst,
    int n_nodes, int n_edges)
{
    __shared__ int s_warpsum[32];
    __shared__ int s_blockoff;

    const int tid  = threadIdx.x;
    const int gtid = blockIdx.x * BT + tid;
    const int lane = tid & 31, wid = tid >> 5;

    // Phase 0: zero degrees; warp-parallel index-width detection.
    for (int i = gtid; i < n_nodes; i += NT) { g_outdeg[i] = 0; g_indeg[i] = 0; }
    if (blockIdx.x == 0 && wid == 0) {
        // int32 data viewed as u64 packs two random indices -> huge w.p. ~1.
        const unsigned long long* p = (const unsigned long long*)src;
        int k = n_edges < 64 ? n_edges : 64;   // u64 slots safe to read
        bool big = false;
        if (lane < k      && p[lane]      >= (unsigned long long)n_nodes) big = true;
        if (lane + 32 < k && p[lane + 32] >= (unsigned long long)n_nodes) big = true;
        unsigned any = __any_sync(0xFFFFFFFFu, big);
        if (lane == 0) g_is64 = any ? 0 : 1;
    }
    gbar(0);

    const int is64  = g_is64;
    const int npair = (n_edges + 1) >> 1;

    // Phase 1: degree histograms (2 edges/thread, vector index loads).
    for (int t = gtid; t < npair; t += NT) {
        int s0, s1, d0, d1; bool two;
        load_pair(src, dst, t, n_edges, is64, s0, s1, d0, d1, two);
        atomicAdd(&g_outdeg[s0], 1);
        atomicAdd(&g_indeg[d0], 1);
        if (two) { atomicAdd(&g_outdeg[s1], 1); atomicAdd(&g_indeg[d1], 1); }
    }
    gbar(1);

    // Phase 2a: per-block chunk sum of indeg (kept in register v).
    const int chunk = (n_nodes + NB - 1) / NB;   // 338
    const int base  = blockIdx.x * chunk;
    int rem  = n_nodes - base;
    int cntn = rem < 0 ? 0 : (rem < chunk ? rem : chunk);
    int v = (tid < cntn) ? g_indeg[base + tid] : 0;
    {
        int r = v;
        #pragma unroll
        for (int o = 16; o > 0; o >>= 1) r += __shfl_down_sync(0xFFFFFFFFu, r, o);
        if (lane == 0) s_warpsum[wid] = r;
        __syncthreads();
        if (wid == 0) {
            int a = s_warpsum[lane];
            #pragma unroll
            for (int o = 16; o > 0; o >>= 1) a += __shfl_down_sync(0xFFFFFFFFu, a, o);
            if (lane == 0) g_blocksum[blockIdx.x] = a;
        }
    }
    gbar(2);

    // Phase 2b: block offset + block-local exclusive scan -> rowstart/cursor/rsout.
    if (wid == 31) {
        int acc = 0;
        for (int b = lane; b < blockIdx.x; b += 32) acc += g_blocksum[b];
        #pragma unroll
        for (int o = 16; o > 0; o >>= 1) acc += __shfl_down_sync(0xFFFFFFFFu, acc, o);
        if (lane == 0) s_blockoff = acc;
    }
    __syncthreads();
    int inc = v;
    #pragma unroll
    for (int o = 1; o < 32; o <<= 1) {
        int t = __shfl_up_sync(0xFFFFFFFFu, inc, o);
        if (lane >= o) inc += t;
    }
    if (lane == 31) s_warpsum[wid] = inc;
    __syncthreads();
    if (wid == 0) {
        int orig = s_warpsum[lane];
        int sc = orig;
        #pragma unroll
        for (int o = 1; o < 32; o <<= 1) {
            int t = __shfl_up_sync(0xFFFFFFFFu, sc, o);
            if (lane >= o) sc += t;
        }
        s_warpsum[lane] = sc - orig;
    }
    __syncthreads();
    int excl = inc - v + s_warpsum[wid] + s_blockoff;
    if (tid < cntn) {
        int i = base + tid;
        g_rowstart[i] = excl;
        g_cursor[i]   = excl;
        int od = g_outdeg[i]; if (od < 1) od = 1;
        g_rsout[i] = rsqrtf((float)od);
    }
    if (base + tid == n_nodes - 1) g_rowstart[n_nodes] = excl + v;
    gbar_last(3);

    // Phase 3: fill CSR buckets.
    for (int t = gtid; t < npair; t += NT) {
        int s0, s1, d0, d1; bool two;
        load_pair(src, dst, t, n_edges, is64, s0, s1, d0, d1, two);
        int p0 = atomicAdd(&g_cursor[d0], 1);
        g_csr[p0] = s0;
        if (two) {
            int p1 = atomicAdd(&g_cursor[d1], 1);
            g_csr[p1] = s1;
        }
    }
}

// ── Gather: warp-per-node, 2-edge unroll (R4 config: 256 thr, low regs) ──
__global__ void __launch_bounds__(256) k_gather(const float4* __restrict__ x,
                                                float4* __restrict__ out,
                                                int n_nodes) {
    int w = (blockIdx.x * blockDim.x + threadIdx.x) >> 5;
    if (w >= n_nodes) return;
    int lane = threadIdx.x & 31;
    int beg = g_rowstart[w];
    int end = g_rowstart[w + 1];
    float4 acc = make_float4(0.f, 0.f, 0.f, 0.f);
    int j = beg;
    for (; j + 2 <= end; j += 2) {
        int s0 = g_csr[j];
        int s1 = g_csr[j + 1];
        float c0 = g_rsout[s0];
        float c1 = g_rsout[s1];
        if (lane < DV) {
            float4 v0 = x[s0 * DV + lane];
            float4 v1 = x[s1 * DV + lane];
            acc.x = fmaf(v0.x, c0, acc.x); acc.y = fmaf(v0.y, c0, acc.y);
            acc.z = fmaf(v0.z, c0, acc.z); acc.w = fmaf(v0.w, c0, acc.w);
            acc.x = fmaf(v1.x, c1, acc.x); acc.y = fmaf(v1.y, c1, acc.y);
            acc.z = fmaf(v1.z, c1, acc.z); acc.w = fmaf(v1.w, c1, acc.w);
        }
    }
    if (j < end) {
        int s = g_csr[j];
        float c = g_rsout[s];
        if (lane < DV) {
            float4 v = x[s * DV + lane];
            acc.x = fmaf(v.x, c, acc.x); acc.y = fmaf(v.y, c, acc.y);
            acc.z = fmaf(v.z, c, acc.z); acc.w = fmaf(v.w, c, acc.w);
        }
    }
    int deg = end - beg; if (deg < 1) deg = 1;
    float rsin = rsqrtf((float)deg);
    if (lane < DV) {
        acc.x *= rsin; acc.y *= rsin; acc.z *= rsin; acc.w *= rsin;
        out[w * DV + lane] = acc;
    }
}

extern "C" void kernel_launch(void* const* d_in, const int* in_sizes, int n_in,
                              void* d_out, int out_size) {
    const float* x   = (const float*)d_in[0];
    const void*  src = d_in[1];
    const void*  dst = d_in[2];
    float* out = (float*)d_out;

    int n_nodes = in_sizes[0] / DFEAT;   // 50000
    int n_edges = in_sizes[1];           // 800000

    k_aux<<<NB, BT>>>(src, dst, n_nodes, n_edges);
    int gather_threads = n_nodes * 32;
    k_gather<<<(gather_threads + 255) / 256, 256>>>((const float4*)x,
                                                    (float4*)out, n_nodes);
}